// round 6
// baseline (speedup 1.0000x reference)
#include <cuda_runtime.h>

// B=32, R=64 (theta j, phi p), L=32, M=63, spins=2, C=64. All inputs f32.
#define TWO_PI_F 6.28318530717958647692f

#define SZ_SPHERE 16777216
#define SZ_KERNEL 524288
#define SZ_LEG    258048
#define SZ_W      64

// Packed (l,m): row(l,b,mm) = 32*l*l + b*(2l+1) + mm, mm = m-31+l in [0,2l].
// Total rows 32768, row width 128 (spin*64 + chan).
#define N_A 4194304            // 32768*128 float2
#define N_G 16515072           // 32*2*63*64*64 float2 (126 MiB)

__device__ float2 g_G   [N_G];
__device__ float2 g_Ain [N_A];
__device__ float2 g_Aout[N_A];

// ---------------------------------------------------------------------------
// k1: forward DFT over phi.
// G[b,i,m,j,c] = (1/64) sum_p f[b,j,p,i,c] e^{-i 2pi (m-31) p / 64}
// ---------------------------------------------------------------------------
__global__ void k1_dft(const float* __restrict__ fre, const float* __restrict__ fim) {
    __shared__ float2 sh_f[64][64];   // [p][c]
    __shared__ float2 sh_tw[64];

    int bid = blockIdx.x;
    int j = bid & 63, bi = bid >> 6;
    int i = bi & 1,  b = bi >> 1;
    int tid = threadIdx.x;

    if (tid < 64) {
        float s, c;
        sincosf(-TWO_PI_F * (float)tid / 64.0f, &s, &c);
        sh_tw[tid] = make_float2(c * (1.0f / 64.0f), s * (1.0f / 64.0f));
    }
    long base = (long)(b * 64 + j) * 8192;       // (p*2+i)*64 + c
    for (int e = tid; e < 4096; e += 256) {
        int p = e >> 6, c = e & 63;
        long a = base + (long)(p * 2 + i) * 64 + c;   // <= 16,777,215
        sh_f[p][c] = make_float2(fre[a], fim[a]);
    }
    __syncthreads();

    int c = tid & 63, mq = tid >> 6;             // thread m-set: mq + 4u
    float2 acc[16];
    #pragma unroll
    for (int u = 0; u < 16; u++) acc[u] = make_float2(0.0f, 0.0f);

    int mv0 = mq - 31;
    int kp0 = 0, delta = 0;                      // (mv0*p)&63, (4p)&63
    for (int p = 0; p < 64; p++) {
        float2 f = sh_f[p][c];
        int k = kp0;
        #pragma unroll
        for (int u = 0; u < 16; u++) {
            float2 tw = sh_tw[k];
            acc[u].x += f.x * tw.x - f.y * tw.y;
            acc[u].y += f.x * tw.y + f.y * tw.x;
            k = (k + delta) & 63;
        }
        kp0   = (kp0 + mv0) & 63;
        delta = (delta + 4) & 63;
    }
    long gbase = (long)bi * 63 * 4096 + (long)j * 64 + c;
    #pragma unroll
    for (int u = 0; u < 16; u++) {
        int m = mq + 4 * u;
        if (m < 63) g_G[gbase + (long)m * 4096] = acc[u];   // <= 16,515,071
    }
}

// ---------------------------------------------------------------------------
// k2: theta quadrature, packed output.
// A_in[row(l,b,mm), i*64+c] = sum_j (2pi w_j leg_in[i,l,m,j]) G[b,i,m,j,c]
// ---------------------------------------------------------------------------
__global__ void k2_theta(const float* __restrict__ leg_in, const float* __restrict__ w) {
    __shared__ float2 sh_g[64][64];   // [j][c]
    __shared__ float  sh_P[32][64];   // [l][j]

    int m = blockIdx.x, i = blockIdx.y, b = blockIdx.z;
    int tid = threadIdx.x;
    int bi = b * 2 + i;

    long gbase = ((long)bi * 63 + m) * 4096;
    for (int e = tid; e < 4096; e += 256) sh_g[e >> 6][e & 63] = g_G[gbase + e];
    for (int e = tid; e < 2048; e += 256) {
        int l = e >> 6, jj = e & 63;
        sh_P[l][jj] = TWO_PI_F * w[jj] * leg_in[((i * 32 + l) * 63 + m) * 64 + jj];
    }
    __syncthreads();

    int c = tid & 63, lq = tid >> 6;
    int lmin = (m <= 31) ? (31 - m) : (m - 31);
    int nv = 32 - lmin;
    float2 acc[8];
    #pragma unroll
    for (int u = 0; u < 8; u++) acc[u] = make_float2(0.0f, 0.0f);

    for (int jj = 0; jj < 64; jj++) {
        float2 g = sh_g[jj][c];
        #pragma unroll
        for (int u = 0; u < 8; u++) {
            int l = lmin + lq + 4 * u;
            float pl = (l < 32) ? sh_P[l][jj] : 0.0f;
            acc[u].x += pl * g.x;
            acc[u].y += pl * g.y;
        }
    }
    #pragma unroll
    for (int u = 0; u < 8; u++) {
        int lv = lq + 4 * u;
        if (lv < nv) {
            int l = lmin + lv;
            int mm = (m - 31) + l;                    // in [0, 2l]
            long row = (long)(32 * l * l) + b * (2 * l + 1) + mm;   // <= 32767
            g_Ain[row * 128 + i * 64 + c] = acc[u];
        }
    }
}

// ---------------------------------------------------------------------------
// k3: per-l complex GEMM on packed rows.
// A_out[row, o*64+d] = sum_ic A_in[row, ic] * K[l,i,o,c,d]
// ---------------------------------------------------------------------------
__global__ void k3_gemm(const float* __restrict__ kre, const float* __restrict__ kim) {
    __shared__ float2 sA[16][64];
    __shared__ float2 sB[16][64];

    int o = blockIdx.x, rt = blockIdx.y, l = blockIdx.z;
    int nrow = 32 * (2 * l + 1);
    int row0 = rt * 64;
    if (row0 >= nrow) return;

    int tid = threadIdx.x, tx = tid & 15, ty = tid >> 4;
    float2 acc[4][4];
    #pragma unroll
    for (int ri = 0; ri < 4; ri++)
        #pragma unroll
        for (int ci = 0; ci < 4; ci++) acc[ri][ci] = make_float2(0.0f, 0.0f);

    long Abase = (long)(32 * l * l) * 128;
    long wbase = (long)l * 16384 + (long)o * 4096;   // + i*8192 + c*64 + d

    for (int k0 = 0; k0 < 128; k0 += 16) {
        #pragma unroll
        for (int t = 0; t < 4; t++) {
            int e = tid + t * 256;
            int rr = e >> 4, kk = e & 15;
            int grow = row0 + rr;
            float2 v = make_float2(0.0f, 0.0f);
            if (grow < nrow) v = g_Ain[Abase + (long)grow * 128 + k0 + kk];
            sA[kk][rr] = v;
        }
        #pragma unroll
        for (int t = 0; t < 4; t++) {
            int e = tid + t * 256;
            int kk = e >> 6, col = e & 63;
            int ic = k0 + kk;
            long a = wbase + (long)(ic >> 6) * 8192 + (ic & 63) * 64 + col;  // <= 524,287
            sB[kk][col] = make_float2(kre[a], kim[a]);
        }
        __syncthreads();
        #pragma unroll
        for (int kk = 0; kk < 16; kk++) {
            float2 av[4], bv[4];
            #pragma unroll
            for (int u = 0; u < 4; u++) av[u] = sA[kk][ty + 16 * u];
            #pragma unroll
            for (int u = 0; u < 4; u++) bv[u] = sB[kk][tx + 16 * u];
            #pragma unroll
            for (int ri = 0; ri < 4; ri++)
                #pragma unroll
                for (int ci = 0; ci < 4; ci++) {
                    acc[ri][ci].x += av[ri].x * bv[ci].x - av[ri].y * bv[ci].y;
                    acc[ri][ci].y += av[ri].x * bv[ci].y + av[ri].y * bv[ci].x;
                }
        }
        __syncthreads();
    }
    #pragma unroll
    for (int ri = 0; ri < 4; ri++) {
        int grow = row0 + ty + 16 * ri;
        if (grow < nrow) {
            #pragma unroll
            for (int ci = 0; ci < 4; ci++)
                g_Aout[Abase + (long)grow * 128 + o * 64 + tx + 16 * ci] = acc[ri][ci];
        }
    }
}

// ---------------------------------------------------------------------------
// k45: fused inverse theta + inverse phi DFT. One block per (b,o,j).
// H[m,d] = sum_l leg_out[o,l,m,j] * A_out[row(l,b,m-31+l), o*64+d]   (shared)
// out[b,j,p,o,d] = sum_m H[m,d] e^{+i 2pi (m-31) p / 64}
// mode 0: d_out is float32 REAL PART, out_cap in floats (covers all elements).
// mode 1: d_out is interleaved complex (float2), out_cap in float2.
// ---------------------------------------------------------------------------
__global__ void k45_out(const float* __restrict__ leg_out, void* __restrict__ dout,
                        int mode, long out_cap) {
    __shared__ float  sh_Q[32][64];   // [l][m], col 63 zero
    __shared__ float2 sh_H[63][64];   // [m][d]
    __shared__ float2 sh_tw[64];

    int bid = blockIdx.x;             // ((b*2+o)*64 + j)
    int j = bid & 63;
    int bo = bid >> 6;
    int o = bo & 1, b = bo >> 1;
    int tid = threadIdx.x;
    int d = tid & 63, tq = tid >> 6;

    if (tid < 64) {
        float s, c;
        sincosf(TWO_PI_F * (float)tid / 64.0f, &s, &c);
        sh_tw[tid] = make_float2(c, s);
    }
    for (int e = tid; e < 2048; e += 256) {
        int l = e >> 6, mc = e & 63;
        float q = 0.0f;
        if (mc < 63) q = leg_out[((o * 32 + l) * 63 + mc) * 64 + j];
        sh_Q[l][mc] = q;
    }
    __syncthreads();

    // Phase A: H[m][d]
    float2 acc[16];
    #pragma unroll
    for (int u = 0; u < 16; u++) acc[u] = make_float2(0.0f, 0.0f);

    for (int l = 0; l < 32; l++) {
        int tl = 2 * l + 1;
        long lbase = (long)(32 * l * l) * 128 + o * 64 + d;
        long brow = (long)b * tl;
        #pragma unroll
        for (int u = 0; u < 16; u++) {
            int m = tq + 4 * u;
            float q = sh_Q[l][m];                          // 0 outside triangle
            int mm = m - 31 + l;
            mm = mm < 0 ? 0 : (mm > 2 * l ? 2 * l : mm);   // clamp, q==0 kills
            float2 a = g_Aout[lbase + (brow + mm) * 128];
            acc[u].x += q * a.x;
            acc[u].y += q * a.y;
        }
    }
    #pragma unroll
    for (int u = 0; u < 16; u++) {
        int m = tq + 4 * u;
        if (m < 63) sh_H[m][d] = acc[u];
    }
    __syncthreads();

    // Phase B: inverse DFT over m, thread owns p = tq + 4v.
    float2 po[16];
    #pragma unroll
    for (int v = 0; v < 16; v++) po[v] = make_float2(0.0f, 0.0f);

    int base  = (-31 * tq) & 63;
    int delta = (-124) & 63;
    for (int m = 0; m < 63; m++) {
        float2 h = sh_H[m][d];
        int k = base;
        #pragma unroll
        for (int v = 0; v < 16; v++) {
            float2 tw = sh_tw[k];
            po[v].x += h.x * tw.x - h.y * tw.y;
            po[v].y += h.x * tw.y + h.y * tw.x;
            k = (k + delta) & 63;
        }
        base  = (base + tq) & 63;
        delta = (delta + 4) & 63;
    }
    long bj = (long)(b * 64 + j);
    if (mode == 1) {
        float2* out2 = (float2*)dout;
        #pragma unroll
        for (int v = 0; v < 16; v++) {
            int p = tq + 4 * v;
            long oi = ((bj * 64 + p) * 2 + o) * 64 + d;
            if (oi < out_cap) out2[oi] = po[v];
        }
    } else {
        float* out1 = (float*)dout;
        #pragma unroll
        for (int v = 0; v < 16; v++) {
            int p = tq + 4 * v;
            long oi = ((bj * 64 + p) * 2 + o) * 64 + d;
            if (oi < out_cap) out1[oi] = po[v].x;          // real part
        }
    }
}

// ---------------------------------------------------------------------------
// Host: identify inputs by element count; re/im tie-break by full-signature
// order (alphabetical = im first, dict = re first). Output mode from out_size.
// ---------------------------------------------------------------------------
extern "C" void kernel_launch(void* const* d_in, const int* in_sizes, int n_in,
                              void* d_out, int out_size) {
    if (n_in < 7) return;

    const float* sph[2] = {0, 0};
    const float* ker[2] = {0, 0};
    const float* leg[2] = {0, 0};
    const float* w = 0;
    int ns = 0, nk = 0, nl = 0;

    for (int t = 0; t < n_in; t++) {
        const float* p = (const float*)d_in[t];
        int sz = in_sizes[t];
        if (sz == SZ_SPHERE && ns < 2) sph[ns++] = p;
        else if (sz == SZ_KERNEL && nk < 2) ker[nk++] = p;
        else if (sz == SZ_LEG && nl < 2) leg[nl++] = p;
        else if (sz == SZ_W && !w) w = p;
    }
    if (ns != 2 || nk != 2 || nl != 2 || !w) return;

    bool alpha = (n_in == 7 &&
                  in_sizes[0] == SZ_KERNEL && in_sizes[1] == SZ_KERNEL &&
                  in_sizes[2] == SZ_LEG    && in_sizes[3] == SZ_LEG &&
                  in_sizes[4] == SZ_W      &&
                  in_sizes[5] == SZ_SPHERE && in_sizes[6] == SZ_SPHERE);

    const float *fre, *fim, *kre, *kim;
    if (alpha) { fim = sph[0]; fre = sph[1]; kim = ker[0]; kre = ker[1]; }
    else       { fre = sph[0]; fim = sph[1]; kre = ker[0]; kim = ker[1]; }
    const float* leg_in = leg[0];
    const float* leg_out = leg[1];

    // Output encoding:
    //   out_size == 16,777,216 -> f32 buffer, REAL PART of the complex result
    //   out_size == 33,554,432 -> f32 pairs = interleaved complex (float2)
    //   anything else          -> treat as f32 real, capped (cannot overrun)
    int mode;
    long cap;
    if (out_size == 33554432)      { mode = 1; cap = 16777216; }     // float2 count
    else if (out_size == 16777216) { mode = 0; cap = 16777216; }     // float count
    else                           { mode = 0; cap = (long)out_size; }

    k1_dft  <<<4096, 256>>>(fre, fim);
    k2_theta<<<dim3(63, 2, 32), 256>>>(leg_in, w);
    k3_gemm <<<dim3(2, 32, 32), 256>>>(kre, kim);
    k45_out <<<4096, 256>>>(leg_out, d_out, mode, cap);
}

// round 7
// speedup vs baseline: 1.3526x; 1.3526x over previous
#include <cuda_runtime.h>

// B=32, R=64 (theta j, phi p), L=32, M=63, spins=2, C=64. All inputs f32.
#define TWO_PI_F 6.28318530717958647692f

#define SZ_SPHERE 16777216
#define SZ_KERNEL 524288
#define SZ_LEG    258048
#define SZ_W      64

// Packed (l,m): row(l,b,mm) = 32*l*l + b*(2l+1) + mm, mm = m-31+l in [0,2l].
#define N_A 4194304            // 32768*128 float2
#define N_G 16515072           // 126 MiB: G (b,i,m,j,c) then reused as H (b,j,o,m,d)

__device__ float2 g_G   [N_G];
__device__ float2 g_Ain [N_A];
__device__ float2 g_Aout[N_A];

typedef unsigned long long ull;

// f32x2 packed helpers (FFMA2 path — sm_103a)
__device__ __forceinline__ ull pk2(float lo, float hi) {
    ull r; asm("mov.b64 %0, {%1,%2};" : "=l"(r) : "f"(lo), "f"(hi)); return r;
}
__device__ __forceinline__ ull ffma2(ull a, ull b, ull c) {
    ull d; asm("fma.rn.f32x2 %0, %1, %2, %3;" : "=l"(d) : "l"(a), "l"(b), "l"(c)); return d;
}
__device__ __forceinline__ float2 upk2(ull v) {
    float2 f; asm("mov.b64 {%0,%1}, %2;" : "=f"(f.x), "=f"(f.y) : "l"(v)); return f;
}

// ---------------------------------------------------------------------------
// k1: forward DFT over phi.
// G[b,i,m,j,c] = (1/64) sum_p f[b,j,p,i,c] e^{-i 2pi (m-31) p / 64}
// Twiddle quads ((c,s),(-s,c)) in 512-entry (8x replicated) shared table.
// ---------------------------------------------------------------------------
__global__ void k1_dft(const float* __restrict__ fre, const float* __restrict__ fim) {
    __shared__ float2    sh_f[64][64];   // [p][c]  32 KB
    __shared__ ulonglong2 sh_tw[512];    // 8 KB

    int bid = blockIdx.x;
    int j = bid & 63, bi = bid >> 6;
    int i = bi & 1,  b = bi >> 1;
    int tid = threadIdx.x;

    for (int e = tid; e < 512; e += 256) {
        int k = e & 63;
        float s, c;
        sincosf(-TWO_PI_F * (float)k / 64.0f, &s, &c);
        c *= (1.0f / 64.0f); s *= (1.0f / 64.0f);
        sh_tw[e] = make_ulonglong2(pk2(c, s), pk2(-s, c));
    }
    long base = (long)(b * 64 + j) * 8192;       // (p*2+i)*64 + c
    for (int e = tid; e < 4096; e += 256) {
        int p = e >> 6, c = e & 63;
        long a = base + (long)(p * 2 + i) * 64 + c;
        sh_f[p][c] = make_float2(fre[a], fim[a]);
    }
    __syncthreads();

    int c = tid & 63, mq = tid >> 6;             // thread m-set: mq + 4u
    ull acc[16];
    #pragma unroll
    for (int u = 0; u < 16; u++) acc[u] = 0ull;

    int mv0 = mq - 31;
    int kp0 = 0, delta = 0;                      // (mv0*p)&63, (4p)&63
    for (int p = 0; p < 64; p++) {
        float2 f = sh_f[p][c];
        ull fxx = pk2(f.x, f.x), fyy = pk2(f.y, f.y);
        int k = kp0;
        #pragma unroll
        for (int u = 0; u < 16; u++) {
            if (u == 8) k = (kp0 + 8 * delta) & 63;  // re-anchor: k stays < 512
            ulonglong2 q = sh_tw[k];
            acc[u] = ffma2(fxx, q.x, ffma2(fyy, q.y, acc[u]));
            k += delta;
        }
        kp0   = (kp0 + mv0) & 63;
        delta = (delta + 4) & 63;
    }
    long gbase = (long)bi * 63 * 4096 + (long)j * 64 + c;
    #pragma unroll
    for (int u = 0; u < 16; u++) {
        int m = mq + 4 * u;
        if (m < 63) g_G[gbase + (long)m * 4096] = upk2(acc[u]);
    }
}

// ---------------------------------------------------------------------------
// k2: theta quadrature, packed output.
// A_in[row(l,b,mm), i*64+c] = sum_j (2pi w_j leg_in[i,l,m,j]) G[b,i,m,j,c]
// ---------------------------------------------------------------------------
__global__ void k2_theta(const float* __restrict__ leg_in, const float* __restrict__ w) {
    __shared__ float2 sh_g[64][64];   // [j][c]
    __shared__ float  sh_P[32][64];   // [l][j]

    int m = blockIdx.x, i = blockIdx.y, b = blockIdx.z;
    int tid = threadIdx.x;
    int bi = b * 2 + i;

    long gbase = ((long)bi * 63 + m) * 4096;
    for (int e = tid; e < 4096; e += 256) sh_g[e >> 6][e & 63] = g_G[gbase + e];
    for (int e = tid; e < 2048; e += 256) {
        int l = e >> 6, jj = e & 63;
        sh_P[l][jj] = TWO_PI_F * w[jj] * leg_in[((i * 32 + l) * 63 + m) * 64 + jj];
    }
    __syncthreads();

    int c = tid & 63, lq = tid >> 6;
    int lmin = (m <= 31) ? (31 - m) : (m - 31);
    int nv = 32 - lmin;
    float2 acc[8];
    #pragma unroll
    for (int u = 0; u < 8; u++) acc[u] = make_float2(0.0f, 0.0f);

    for (int jj = 0; jj < 64; jj++) {
        float2 g = sh_g[jj][c];
        #pragma unroll
        for (int u = 0; u < 8; u++) {
            int l = lmin + lq + 4 * u;
            float pl = (l < 32) ? sh_P[l][jj] : 0.0f;
            acc[u].x += pl * g.x;
            acc[u].y += pl * g.y;
        }
    }
    #pragma unroll
    for (int u = 0; u < 8; u++) {
        int lv = lq + 4 * u;
        if (lv < nv) {
            int l = lmin + lv;
            int mm = (m - 31) + l;
            long row = (long)(32 * l * l) + b * (2 * l + 1) + mm;
            g_Ain[row * 128 + i * 64 + c] = acc[u];
        }
    }
}

// ---------------------------------------------------------------------------
// k3: per-l complex GEMM on packed rows (FFMA2).
// A_out[row, o*64+d] = sum_ic A_in[row, ic] * K[l,i,o,c,d]
// sB holds pre-packed quads ((b.x,b.y),(-b.y,b.x)).
// ---------------------------------------------------------------------------
__global__ void k3_gemm(const float* __restrict__ kre, const float* __restrict__ kim) {
    __shared__ float2     sA[16][64];   // 8 KB
    __shared__ ulonglong2 sB[16][64];   // 16 KB

    int o = blockIdx.x, rt = blockIdx.y, l = blockIdx.z;
    int nrow = 32 * (2 * l + 1);
    int row0 = rt * 64;
    if (row0 >= nrow) return;

    int tid = threadIdx.x, tx = tid & 15, ty = tid >> 4;
    ull acc[4][4];
    #pragma unroll
    for (int ri = 0; ri < 4; ri++)
        #pragma unroll
        for (int ci = 0; ci < 4; ci++) acc[ri][ci] = 0ull;

    long Abase = (long)(32 * l * l) * 128;
    long wbase = (long)l * 16384 + (long)o * 4096;   // + i*8192 + c*64 + d

    for (int k0 = 0; k0 < 128; k0 += 16) {
        #pragma unroll
        for (int t = 0; t < 4; t++) {
            int e = tid + t * 256;
            int rr = e >> 4, kk = e & 15;
            int grow = row0 + rr;
            float2 v = make_float2(0.0f, 0.0f);
            if (grow < nrow) v = g_Ain[Abase + (long)grow * 128 + k0 + kk];
            sA[kk][rr] = v;
        }
        #pragma unroll
        for (int t = 0; t < 4; t++) {
            int e = tid + t * 256;
            int kk = e >> 6, col = e & 63;
            int ic = k0 + kk;
            long a = wbase + (long)(ic >> 6) * 8192 + (ic & 63) * 64 + col;
            float br = kre[a], bim = kim[a];
            sB[kk][col] = make_ulonglong2(pk2(br, bim), pk2(-bim, br));
        }
        __syncthreads();
        #pragma unroll
        for (int kk = 0; kk < 16; kk++) {
            ull axx[4], ayy[4];
            ulonglong2 bq[4];
            #pragma unroll
            for (int u = 0; u < 4; u++) {
                float2 a = sA[kk][ty + 16 * u];
                axx[u] = pk2(a.x, a.x);
                ayy[u] = pk2(a.y, a.y);
            }
            #pragma unroll
            for (int u = 0; u < 4; u++) bq[u] = sB[kk][tx + 16 * u];
            #pragma unroll
            for (int ri = 0; ri < 4; ri++)
                #pragma unroll
                for (int ci = 0; ci < 4; ci++)
                    acc[ri][ci] = ffma2(axx[ri], bq[ci].x,
                                  ffma2(ayy[ri], bq[ci].y, acc[ri][ci]));
        }
        __syncthreads();
    }
    #pragma unroll
    for (int ri = 0; ri < 4; ri++) {
        int grow = row0 + ty + 16 * ri;
        if (grow < nrow) {
            #pragma unroll
            for (int ci = 0; ci < 4; ci++)
                g_Aout[Abase + (long)grow * 128 + o * 64 + tx + 16 * ci] = upk2(acc[ri][ci]);
        }
    }
}

// ---------------------------------------------------------------------------
// k4: inverse theta (UN-fused: A_out amortized over all 64 j in shared).
// H[b,j,o,m,d] = sum_{l>=lmin} leg_out[o,l,m,j] * A_out[row(l,b,m-31+l), o*64+d]
// H reuses g_G (G dead after k2). One block per (m,o,b).
// ---------------------------------------------------------------------------
__global__ void k4_itheta(const float* __restrict__ leg_out) {
    __shared__ float2 sh_a[32][64];   // [l][d]
    __shared__ float  sh_Q[32][64];   // [l][j]

    int m = blockIdx.x, o = blockIdx.y, b = blockIdx.z;
    int tid = threadIdx.x;
    int lmin = (m <= 31) ? (31 - m) : (m - 31);

    for (int e = tid; e < 2048; e += 256) {
        int l = e >> 6, d = e & 63;
        float2 v = make_float2(0.0f, 0.0f);
        if (l >= lmin) {
            int mm = m - 31 + l;
            long row = (long)(32 * l * l) + b * (2 * l + 1) + mm;
            v = g_Aout[row * 128 + o * 64 + d];
        }
        sh_a[l][d] = v;
    }
    for (int e = tid; e < 2048; e += 256) {
        int l = e >> 6, j = e & 63;
        sh_Q[l][j] = leg_out[((o * 32 + l) * 63 + m) * 64 + j];
    }
    __syncthreads();

    int d = tid & 63, jq = tid >> 6;
    float2 acc[16];
    #pragma unroll
    for (int u = 0; u < 16; u++) acc[u] = make_float2(0.0f, 0.0f);

    for (int l = lmin; l < 32; l++) {
        float2 a = sh_a[l][d];
        #pragma unroll
        for (int u = 0; u < 16; u++) {
            float q = sh_Q[l][jq + 4 * u];
            acc[u].x += q * a.x;
            acc[u].y += q * a.y;
        }
    }
    #pragma unroll
    for (int u = 0; u < 16; u++) {
        int j = jq + 4 * u;
        g_G[(long)((b * 64 + j) * 2 + o) * 4032 + m * 64 + d] = acc[u];   // H
    }
}

// ---------------------------------------------------------------------------
// k5: inverse phi DFT (FFMA2 + replicated twiddle quads).
// out[b,j,p,o,d] = sum_m H[m,d] e^{+i 2pi (m-31) p / 64}
// mode 0: f32 real part; mode 1: interleaved complex float2.
// ---------------------------------------------------------------------------
__global__ void k5_idft(void* __restrict__ dout, int mode, long out_cap) {
    __shared__ float2     sh_h[63][64];  // 31.5 KB
    __shared__ ulonglong2 sh_tw[512];    // 8 KB

    int bid = blockIdx.x;             // (b*64+j)*2 + o  (matches k4's H layout)
    int tid = threadIdx.x;
    int d = tid & 63, tq = tid >> 6;

    for (int e = tid; e < 512; e += 256) {
        int k = e & 63;
        float s, c;
        sincosf(TWO_PI_F * (float)k / 64.0f, &s, &c);
        sh_tw[e] = make_ulonglong2(pk2(c, s), pk2(-s, c));
    }
    long hbase = (long)bid * 4032;
    for (int e = tid; e < 4032; e += 256) sh_h[e >> 6][e & 63] = g_G[hbase + e];
    __syncthreads();

    ull po[16];
    #pragma unroll
    for (int v = 0; v < 16; v++) po[v] = 0ull;

    int base  = (-31 * tq) & 63;
    int delta = (-124) & 63;
    for (int m = 0; m < 63; m++) {
        float2 h = sh_h[m][d];
        ull hxx = pk2(h.x, h.x), hyy = pk2(h.y, h.y);
        int k = base;
        #pragma unroll
        for (int v = 0; v < 16; v++) {
            if (v == 8) k = (base + 8 * delta) & 63;   // keep k < 512
            ulonglong2 q = sh_tw[k];
            po[v] = ffma2(hxx, q.x, ffma2(hyy, q.y, po[v]));
            k += delta;
        }
        base  = (base + tq) & 63;
        delta = (delta + 4) & 63;
    }
    int o = bid & 1;
    long bj = (long)(bid >> 1);
    if (mode == 1) {
        float2* out2 = (float2*)dout;
        #pragma unroll
        for (int v = 0; v < 16; v++) {
            int p = tq + 4 * v;
            long oi = ((bj * 64 + p) * 2 + o) * 64 + d;
            if (oi < out_cap) out2[oi] = upk2(po[v]);
        }
    } else {
        float* out1 = (float*)dout;
        #pragma unroll
        for (int v = 0; v < 16; v++) {
            int p = tq + 4 * v;
            long oi = ((bj * 64 + p) * 2 + o) * 64 + d;
            if (oi < out_cap) out1[oi] = upk2(po[v]).x;   // real part
        }
    }
}

// ---------------------------------------------------------------------------
// Host dispatch (identical to the passing R6 logic).
// ---------------------------------------------------------------------------
extern "C" void kernel_launch(void* const* d_in, const int* in_sizes, int n_in,
                              void* d_out, int out_size) {
    if (n_in < 7) return;

    const float* sph[2] = {0, 0};
    const float* ker[2] = {0, 0};
    const float* leg[2] = {0, 0};
    const float* w = 0;
    int ns = 0, nk = 0, nl = 0;

    for (int t = 0; t < n_in; t++) {
        const float* p = (const float*)d_in[t];
        int sz = in_sizes[t];
        if (sz == SZ_SPHERE && ns < 2) sph[ns++] = p;
        else if (sz == SZ_KERNEL && nk < 2) ker[nk++] = p;
        else if (sz == SZ_LEG && nl < 2) leg[nl++] = p;
        else if (sz == SZ_W && !w) w = p;
    }
    if (ns != 2 || nk != 2 || nl != 2 || !w) return;

    bool alpha = (n_in == 7 &&
                  in_sizes[0] == SZ_KERNEL && in_sizes[1] == SZ_KERNEL &&
                  in_sizes[2] == SZ_LEG    && in_sizes[3] == SZ_LEG &&
                  in_sizes[4] == SZ_W      &&
                  in_sizes[5] == SZ_SPHERE && in_sizes[6] == SZ_SPHERE);

    const float *fre, *fim, *kre, *kim;
    if (alpha) { fim = sph[0]; fre = sph[1]; kim = ker[0]; kre = ker[1]; }
    else       { fre = sph[0]; fim = sph[1]; kre = ker[0]; kim = ker[1]; }
    const float* leg_in = leg[0];
    const float* leg_out = leg[1];

    int mode;
    long cap;
    if (out_size == 33554432)      { mode = 1; cap = 16777216; }   // float2 count
    else if (out_size == 16777216) { mode = 0; cap = 16777216; }   // float count
    else                           { mode = 0; cap = (long)out_size; }

    k1_dft   <<<4096, 256>>>(fre, fim);
    k2_theta <<<dim3(63, 2, 32), 256>>>(leg_in, w);
    k3_gemm  <<<dim3(2, 32, 32), 256>>>(kre, kim);
    k4_itheta<<<dim3(63, 2, 32), 256>>>(leg_out);
    k5_idft  <<<4096, 256>>>(d_out, mode, cap);
}

// round 8
// speedup vs baseline: 1.5153x; 1.1203x over previous
#include <cuda_runtime.h>

// B=32, R=64 (theta j, phi p), L=32, M=63, spins=2, C=64. All inputs f32.
#define TWO_PI_F 6.28318530717958647692f

#define SZ_SPHERE 16777216
#define SZ_KERNEL 524288
#define SZ_LEG    258048
#define SZ_W      64

// Packed (l,m): row(l,b,mm) = 32*l*l + b*(2l+1) + mm, mm = m-31+l in [0,2l].
#define N_A 4194304            // 32768*128 float2
#define N_G 16515072           // 126 MiB: G (b,i,m,j,c) then reused as H (b,j,o,m,d)

__device__ float2 g_G   [N_G];
__device__ float2 g_Ain [N_A];
__device__ float2 g_Aout[N_A];

typedef unsigned long long ull;

__device__ __forceinline__ ull pk2(float lo, float hi) {
    ull r; asm("mov.b64 %0, {%1,%2};" : "=l"(r) : "f"(lo), "f"(hi)); return r;
}
__device__ __forceinline__ ull ffma2(ull a, ull b, ull c) {
    ull d; asm("fma.rn.f32x2 %0, %1, %2, %3;" : "=l"(d) : "l"(a), "l"(b), "l"(c)); return d;
}
__device__ __forceinline__ float2 upk2(ull v) {
    float2 f; asm("mov.b64 {%0,%1}, %2;" : "=f"(f.x), "=f"(f.y) : "l"(v)); return f;
}
// complex combine from P/Q split accumulators: (P.x - Q.y, P.y + Q.x)
__device__ __forceinline__ float2 pq(ull P, ull Q) {
    float2 p = upk2(P), q = upk2(Q);
    return make_float2(p.x - q.y, p.y + q.x);
}

// ---------------------------------------------------------------------------
// k1: forward DFT over phi.  G[b,i,m,j,c] = (1/64) sum_p f[b,j,p,i,c] e^{-i2pi(m-31)p/64}
// Thread: 4 channels (c4..c4+3) x 4 m-values. P/Q split; tw table ((c,c),(s,s)).
// ---------------------------------------------------------------------------
__global__ void k1_dft(const float* __restrict__ fre, const float* __restrict__ fim) {
    __shared__ float2     sh_f[64][64];   // [p][c]  32 KB
    __shared__ ulonglong2 sh_tw[512];     // ((c,c),(s,s)), 8x replicated, 8 KB

    int bid = blockIdx.x;
    int j = bid & 63, bi = bid >> 6;
    int i = bi & 1,  b = bi >> 1;
    int tid = threadIdx.x;

    for (int e = tid; e < 512; e += 256) {
        int k = e & 63;
        float s, c;
        sincosf(-TWO_PI_F * (float)k / 64.0f, &s, &c);
        c *= (1.0f / 64.0f); s *= (1.0f / 64.0f);
        sh_tw[e] = make_ulonglong2(pk2(c, c), pk2(s, s));
    }
    long base = (long)(b * 64 + j) * 8192;       // (p*2+i)*64 + c
    for (int e = tid; e < 4096; e += 256) {
        int p = e >> 6, c = e & 63;
        long a = base + (long)(p * 2 + i) * 64 + c;
        sh_f[p][c] = make_float2(fre[a], fim[a]);
    }
    __syncthreads();

    int cq = tid & 15, mg = tid >> 4;            // c4 = 4*cq; m = mg + 16u
    int c4 = cq * 4;
    ull accP[4][4], accQ[4][4];
    #pragma unroll
    for (int u = 0; u < 4; u++)
        #pragma unroll
        for (int cc = 0; cc < 4; cc++) { accP[u][cc] = 0ull; accQ[u][cc] = 0ull; }

    int mv0 = mg - 31;
    int kb = 0, d16 = 0;                         // ((mg-31)p)&63, (16p)&63
    for (int p = 0; p < 64; p++) {
        ulonglong2 fA = *(const ulonglong2*)&sh_f[p][c4];      // c4, c4+1
        ulonglong2 fB = *(const ulonglong2*)&sh_f[p][c4 + 2];  // c4+2, c4+3
        ull f[4] = { fA.x, fA.y, fB.x, fB.y };
        int k = kb;
        #pragma unroll
        for (int u = 0; u < 4; u++) {
            ulonglong2 q = sh_tw[k];             // k <= 63 + 3*48 < 512
            #pragma unroll
            for (int cc = 0; cc < 4; cc++) {
                accP[u][cc] = ffma2(q.x, f[cc], accP[u][cc]);
                accQ[u][cc] = ffma2(q.y, f[cc], accQ[u][cc]);
            }
            k += d16;
        }
        kb  = (kb + mv0) & 63;
        d16 = (d16 + 16) & 63;
    }
    #pragma unroll
    for (int u = 0; u < 4; u++) {
        int m = mg + 16 * u;
        if (m < 63) {
            float2 r0 = pq(accP[u][0], accQ[u][0]);
            float2 r1 = pq(accP[u][1], accQ[u][1]);
            float2 r2 = pq(accP[u][2], accQ[u][2]);
            float2 r3 = pq(accP[u][3], accQ[u][3]);
            float4* dst = (float4*)&g_G[(((long)bi * 63 + m) * 64 + j) * 64 + c4];
            dst[0] = make_float4(r0.x, r0.y, r1.x, r1.y);
            dst[1] = make_float4(r2.x, r2.y, r3.x, r3.y);
        }
    }
}

// ---------------------------------------------------------------------------
// k2: theta quadrature, packed output (unchanged from R7).
// ---------------------------------------------------------------------------
__global__ void k2_theta(const float* __restrict__ leg_in, const float* __restrict__ w) {
    __shared__ float2 sh_g[64][64];   // [j][c]
    __shared__ float  sh_P[32][64];   // [l][j]

    int m = blockIdx.x, i = blockIdx.y, b = blockIdx.z;
    int tid = threadIdx.x;
    int bi = b * 2 + i;

    long gbase = ((long)bi * 63 + m) * 4096;
    for (int e = tid; e < 4096; e += 256) sh_g[e >> 6][e & 63] = g_G[gbase + e];
    for (int e = tid; e < 2048; e += 256) {
        int l = e >> 6, jj = e & 63;
        sh_P[l][jj] = TWO_PI_F * w[jj] * leg_in[((i * 32 + l) * 63 + m) * 64 + jj];
    }
    __syncthreads();

    int c = tid & 63, lq = tid >> 6;
    int lmin = (m <= 31) ? (31 - m) : (m - 31);
    int nv = 32 - lmin;
    float2 acc[8];
    #pragma unroll
    for (int u = 0; u < 8; u++) acc[u] = make_float2(0.0f, 0.0f);

    for (int jj = 0; jj < 64; jj++) {
        float2 g = sh_g[jj][c];
        #pragma unroll
        for (int u = 0; u < 8; u++) {
            int l = lmin + lq + 4 * u;
            float pl = (l < 32) ? sh_P[l][jj] : 0.0f;
            acc[u].x += pl * g.x;
            acc[u].y += pl * g.y;
        }
    }
    #pragma unroll
    for (int u = 0; u < 8; u++) {
        int lv = lq + 4 * u;
        if (lv < nv) {
            int l = lmin + lv;
            int mm = (m - 31) + l;
            long row = (long)(32 * l * l) + b * (2 * l + 1) + mm;
            g_Ain[row * 128 + i * 64 + c] = acc[u];
        }
    }
}

// ---------------------------------------------------------------------------
// k3: per-l complex GEMM on packed rows. P/Q split:
// sB quads ((br,br),(bi,bi)); sA natural packed (a.x,a.y).
// ---------------------------------------------------------------------------
__global__ void k3_gemm(const float* __restrict__ kre, const float* __restrict__ kim) {
    __shared__ float2     sA[16][64];   // 8 KB
    __shared__ ulonglong2 sB[16][64];   // 16 KB

    int o = blockIdx.x, rt = blockIdx.y, l = blockIdx.z;
    int nrow = 32 * (2 * l + 1);
    int row0 = rt * 64;
    if (row0 >= nrow) return;

    int tid = threadIdx.x, tx = tid & 15, ty = tid >> 4;
    ull accP[4][4], accQ[4][4];
    #pragma unroll
    for (int ri = 0; ri < 4; ri++)
        #pragma unroll
        for (int ci = 0; ci < 4; ci++) { accP[ri][ci] = 0ull; accQ[ri][ci] = 0ull; }

    long Abase = (long)(32 * l * l) * 128;
    long wbase = (long)l * 16384 + (long)o * 4096;   // + i*8192 + c*64 + d

    for (int k0 = 0; k0 < 128; k0 += 16) {
        #pragma unroll
        for (int t = 0; t < 4; t++) {
            int e = tid + t * 256;
            int rr = e >> 4, kk = e & 15;
            int grow = row0 + rr;
            float2 v = make_float2(0.0f, 0.0f);
            if (grow < nrow) v = g_Ain[Abase + (long)grow * 128 + k0 + kk];
            sA[kk][rr] = v;
        }
        #pragma unroll
        for (int t = 0; t < 4; t++) {
            int e = tid + t * 256;
            int kk = e >> 6, col = e & 63;
            int ic = k0 + kk;
            long a = wbase + (long)(ic >> 6) * 8192 + (ic & 63) * 64 + col;
            float br = kre[a], bim = kim[a];
            sB[kk][col] = make_ulonglong2(pk2(br, br), pk2(bim, bim));
        }
        __syncthreads();
        #pragma unroll
        for (int kk = 0; kk < 16; kk++) {
            ull av[4];
            ulonglong2 bq[4];
            #pragma unroll
            for (int u = 0; u < 4; u++) av[u] = *(const ull*)&sA[kk][ty + 16 * u];
            #pragma unroll
            for (int u = 0; u < 4; u++) bq[u] = sB[kk][tx + 16 * u];
            #pragma unroll
            for (int ri = 0; ri < 4; ri++)
                #pragma unroll
                for (int ci = 0; ci < 4; ci++) {
                    accP[ri][ci] = ffma2(bq[ci].x, av[ri], accP[ri][ci]);
                    accQ[ri][ci] = ffma2(bq[ci].y, av[ri], accQ[ri][ci]);
                }
        }
        __syncthreads();
    }
    #pragma unroll
    for (int ri = 0; ri < 4; ri++) {
        int grow = row0 + ty + 16 * ri;
        if (grow < nrow) {
            #pragma unroll
            for (int ci = 0; ci < 4; ci++)
                g_Aout[Abase + (long)grow * 128 + o * 64 + tx + 16 * ci] =
                    pq(accP[ri][ci], accQ[ri][ci]);
        }
    }
}

// ---------------------------------------------------------------------------
// k4: inverse theta. FFMA2: Q dup table, 1 FFMA2 per cMAC.
// H[b,j,o,m,d] = sum_{l>=lmin} leg_out[o,l,m,j] * A_out[row(l,b,m-31+l), o*64+d]
// ---------------------------------------------------------------------------
__global__ void k4_itheta(const float* __restrict__ leg_out) {
    __shared__ float2 sh_a[32][64];   // [l][d]  16 KB
    __shared__ ull    sh_Q[32][64];   // [l][j] dup (q,q)  16 KB

    int m = blockIdx.x, o = blockIdx.y, b = blockIdx.z;
    int tid = threadIdx.x;
    int lmin = (m <= 31) ? (31 - m) : (m - 31);

    for (int e = tid; e < 2048; e += 256) {
        int l = e >> 6, d = e & 63;
        float2 v = make_float2(0.0f, 0.0f);
        if (l >= lmin) {
            int mm = m - 31 + l;
            long row = (long)(32 * l * l) + b * (2 * l + 1) + mm;
            v = g_Aout[row * 128 + o * 64 + d];
        }
        sh_a[l][d] = v;
    }
    for (int e = tid; e < 2048; e += 256) {
        int l = e >> 6, j = e & 63;
        float q = leg_out[((o * 32 + l) * 63 + m) * 64 + j];
        sh_Q[l][j] = pk2(q, q);
    }
    __syncthreads();

    int d = tid & 63, jq = tid >> 6;
    ull acc[16];
    #pragma unroll
    for (int u = 0; u < 16; u++) acc[u] = 0ull;

    for (int l = lmin; l < 32; l++) {
        ull a = *(const ull*)&sh_a[l][d];
        #pragma unroll
        for (int u = 0; u < 16; u++)
            acc[u] = ffma2(sh_Q[l][jq + 4 * u], a, acc[u]);
    }
    #pragma unroll
    for (int u = 0; u < 16; u++) {
        int j = jq + 4 * u;
        g_G[(long)((b * 64 + j) * 2 + o) * 4032 + m * 64 + d] = upk2(acc[u]);   // H
    }
}

// ---------------------------------------------------------------------------
// k5: inverse phi DFT. P/Q split, 4d x 4p blocking.
// out[b,j,p,o,d] = sum_m H[m,d] e^{+i 2pi (m-31) p / 64}
// ---------------------------------------------------------------------------
__global__ void k5_idft(void* __restrict__ dout, int mode, long out_cap) {
    __shared__ float2     sh_h[63][64];  // 31.5 KB
    __shared__ ulonglong2 sh_tw[512];    // ((c,c),(s,s)) 8 KB

    int bid = blockIdx.x;             // (b*64+j)*2 + o  (matches k4's H layout)
    int tid = threadIdx.x;
    int cq = tid & 15, pg = tid >> 4; // d4 = 4*cq; p = pg + 16v
    int d4 = cq * 4;

    for (int e = tid; e < 512; e += 256) {
        int k = e & 63;
        float s, c;
        sincosf(TWO_PI_F * (float)k / 64.0f, &s, &c);
        sh_tw[e] = make_ulonglong2(pk2(c, c), pk2(s, s));
    }
    long hbase = (long)bid * 4032;
    for (int e = tid; e < 4032; e += 256) sh_h[e >> 6][e & 63] = g_G[hbase + e];
    __syncthreads();

    ull accP[4][4], accQ[4][4];
    #pragma unroll
    for (int v = 0; v < 4; v++)
        #pragma unroll
        for (int cc = 0; cc < 4; cc++) { accP[v][cc] = 0ull; accQ[v][cc] = 0ull; }

    int kb  = (-31 * pg) & 63;        // ((m-31)*pg)&63 at m=0
    int d16 = (16 * (-31)) & 63;      // (16(m-31))&63 at m=0
    for (int m = 0; m < 63; m++) {
        ulonglong2 hA = *(const ulonglong2*)&sh_h[m][d4];
        ulonglong2 hB = *(const ulonglong2*)&sh_h[m][d4 + 2];
        ull h[4] = { hA.x, hA.y, hB.x, hB.y };
        int k = kb;
        #pragma unroll
        for (int v = 0; v < 4; v++) {
            ulonglong2 q = sh_tw[k];             // k <= 63 + 3*48 < 512
            #pragma unroll
            for (int cc = 0; cc < 4; cc++) {
                accP[v][cc] = ffma2(q.x, h[cc], accP[v][cc]);
                accQ[v][cc] = ffma2(q.y, h[cc], accQ[v][cc]);
            }
            k += d16;
        }
        kb  = (kb + pg) & 63;
        d16 = (d16 + 16) & 63;
    }
    int o = bid & 1;
    long bj = (long)(bid >> 1);
    if (mode == 1) {
        float2* out2 = (float2*)dout;
        #pragma unroll
        for (int v = 0; v < 4; v++) {
            int p = pg + 16 * v;
            long oi = ((bj * 64 + p) * 2 + o) * 64 + d4;
            if (oi + 3 < out_cap) {
                float2 r0 = pq(accP[v][0], accQ[v][0]);
                float2 r1 = pq(accP[v][1], accQ[v][1]);
                float2 r2 = pq(accP[v][2], accQ[v][2]);
                float2 r3 = pq(accP[v][3], accQ[v][3]);
                float4* dst = (float4*)&out2[oi];
                dst[0] = make_float4(r0.x, r0.y, r1.x, r1.y);
                dst[1] = make_float4(r2.x, r2.y, r3.x, r3.y);
            }
        }
    } else {
        float* out1 = (float*)dout;
        #pragma unroll
        for (int v = 0; v < 4; v++) {
            int p = pg + 16 * v;
            long oi = ((bj * 64 + p) * 2 + o) * 64 + d4;
            if (oi + 3 < out_cap) {
                float4 r;
                r.x = pq(accP[v][0], accQ[v][0]).x;
                r.y = pq(accP[v][1], accQ[v][1]).x;
                r.z = pq(accP[v][2], accQ[v][2]).x;
                r.w = pq(accP[v][3], accQ[v][3]).x;
                *(float4*)&out1[oi] = r;          // real part
            }
        }
    }
}

// ---------------------------------------------------------------------------
// Host dispatch (identical to the passing R6/R7 logic).
// ---------------------------------------------------------------------------
extern "C" void kernel_launch(void* const* d_in, const int* in_sizes, int n_in,
                              void* d_out, int out_size) {
    if (n_in < 7) return;

    const float* sph[2] = {0, 0};
    const float* ker[2] = {0, 0};
    const float* leg[2] = {0, 0};
    const float* w = 0;
    int ns = 0, nk = 0, nl = 0;

    for (int t = 0; t < n_in; t++) {
        const float* p = (const float*)d_in[t];
        int sz = in_sizes[t];
        if (sz == SZ_SPHERE && ns < 2) sph[ns++] = p;
        else if (sz == SZ_KERNEL && nk < 2) ker[nk++] = p;
        else if (sz == SZ_LEG && nl < 2) leg[nl++] = p;
        else if (sz == SZ_W && !w) w = p;
    }
    if (ns != 2 || nk != 2 || nl != 2 || !w) return;

    bool alpha = (n_in == 7 &&
                  in_sizes[0] == SZ_KERNEL && in_sizes[1] == SZ_KERNEL &&
                  in_sizes[2] == SZ_LEG    && in_sizes[3] == SZ_LEG &&
                  in_sizes[4] == SZ_W      &&
                  in_sizes[5] == SZ_SPHERE && in_sizes[6] == SZ_SPHERE);

    const float *fre, *fim, *kre, *kim;
    if (alpha) { fim = sph[0]; fre = sph[1]; kim = ker[0]; kre = ker[1]; }
    else       { fre = sph[0]; fim = sph[1]; kre = ker[0]; kim = ker[1]; }
    const float* leg_in = leg[0];
    const float* leg_out = leg[1];

    int mode;
    long cap;
    if (out_size == 33554432)      { mode = 1; cap = 16777216; }   // float2 count
    else if (out_size == 16777216) { mode = 0; cap = 16777216; }   // float count
    else                           { mode = 0; cap = (long)out_size; }

    k1_dft   <<<4096, 256>>>(fre, fim);
    k2_theta <<<dim3(63, 2, 32), 256>>>(leg_in, w);
    k3_gemm  <<<dim3(2, 32, 32), 256>>>(kre, kim);
    k4_itheta<<<dim3(63, 2, 32), 256>>>(leg_out);
    k5_idft  <<<4096, 256>>>(d_out, mode, cap);
}

// round 9
// speedup vs baseline: 3.0959x; 2.0431x over previous
#include <cuda_runtime.h>

// B=32, R=64 (theta j, phi p), L=32, M=63, spins=2, C=64. All inputs f32.
#define TWO_PI_F 6.28318530717958647692f

#define SZ_SPHERE 16777216
#define SZ_KERNEL 524288
#define SZ_LEG    258048
#define SZ_W      64

// Packed (l,m): row(l,b,mm) = 32*l*l + b*(2l+1) + mm, mm = m-31+l in [0,2l].
#define N_A 4194304            // 32768*128 float2
#define N_G 16515072           // 126 MiB: G (b,i,m,j,c) then reused as H (b,j,o,m,d)

__device__ float2 g_G   [N_G];
__device__ float2 g_Ain [N_A];
__device__ float2 g_Aout[N_A];

typedef unsigned long long ull;

__device__ __forceinline__ ull pk2(float lo, float hi) {
    ull r; asm("mov.b64 %0, {%1,%2};" : "=l"(r) : "f"(lo), "f"(hi)); return r;
}
__device__ __forceinline__ ull ffma2(ull a, ull b, ull c) {
    ull d; asm("fma.rn.f32x2 %0, %1, %2, %3;" : "=l"(d) : "l"(a), "l"(b), "l"(c)); return d;
}
__device__ __forceinline__ float2 upk2(ull v) {
    float2 f; asm("mov.b64 {%0,%1}, %2;" : "=f"(f.x), "=f"(f.y) : "l"(v)); return f;
}
__device__ __forceinline__ float2 pq(ull P, ull Q) {
    float2 p = upk2(P), q = upk2(Q);
    return make_float2(p.x - q.y, p.y + q.x);
}

// ---------------------------------------------------------------------------
// FFT-64 machinery: radix-2 DIF, fully unrolled, natural input -> bit-reversed
// output. Twiddles W64^k = cos(2pi k/64) - i sin(2pi k/64) from constant table.
// ---------------------------------------------------------------------------
__constant__ float cW[32] = {
    1.0f, 0.99518472667f, 0.98078528040f, 0.95694033573f,
    0.92387953251f, 0.88192126435f, 0.83146961230f, 0.77301045336f,
    0.70710678119f, 0.63439328416f, 0.55557023302f, 0.47139673683f,
    0.38268343236f, 0.29028467725f, 0.19509032202f, 0.09801714033f,
    0.0f, -0.09801714033f, -0.19509032202f, -0.29028467725f,
    -0.38268343236f, -0.47139673683f, -0.55557023302f, -0.63439328416f,
    -0.70710678119f, -0.77301045336f, -0.83146961230f, -0.88192126435f,
    -0.92387953251f, -0.95694033573f, -0.98078528040f, -0.99518472667f };
__constant__ float sW[32] = {
    0.0f, 0.09801714033f, 0.19509032202f, 0.29028467725f,
    0.38268343236f, 0.47139673683f, 0.55557023302f, 0.63439328416f,
    0.70710678119f, 0.77301045336f, 0.83146961230f, 0.88192126435f,
    0.92387953251f, 0.95694033573f, 0.98078528040f, 0.99518472667f,
    1.0f, 0.99518472667f, 0.98078528040f, 0.95694033573f,
    0.92387953251f, 0.88192126435f, 0.83146961230f, 0.77301045336f,
    0.70710678119f, 0.63439328416f, 0.55557023302f, 0.47139673683f,
    0.38268343236f, 0.29028467725f, 0.19509032202f, 0.09801714033f };

__device__ __forceinline__ constexpr int bitrev6(int i) {
    return ((i & 1) << 5) | ((i & 2) << 3) | ((i & 4) << 1)
         | ((i & 8) >> 1) | ((i & 16) >> 3) | ((i & 32) >> 5);
}

template <int LEN, bool INV>
__device__ __forceinline__ void fft_stage(float2* x) {
    constexpr int HALF = LEN / 2;
    constexpr int STEP = 64 / LEN;
    #pragma unroll
    for (int st = 0; st < 64; st += LEN) {
        #pragma unroll
        for (int k = 0; k < HALF; k++) {
            float2 u = x[st + k], v = x[st + k + HALF];
            x[st + k] = make_float2(u.x + v.x, u.y + v.y);
            float2 t = make_float2(u.x - v.x, u.y - v.y);
            if (k == 0) {
                x[st + k + HALF] = t;
            } else {
                float wr = cW[k * STEP];
                float wi = INV ? sW[k * STEP] : -sW[k * STEP];
                x[st + k + HALF] = make_float2(t.x * wr - t.y * wi,
                                               t.x * wi + t.y * wr);
            }
        }
    }
}

template <bool INV>
__device__ __forceinline__ void fft64(float2* x) {
    fft_stage<64, INV>(x);
    fft_stage<32, INV>(x);
    fft_stage<16, INV>(x);
    fft_stage<8,  INV>(x);
    fft_stage<4,  INV>(x);
    fft_stage<2,  INV>(x);
}

// ---------------------------------------------------------------------------
// k1: forward FFT over phi (replaces O(N^2) DFT).
// G[b,i,m,j,c] = X[(m-31)&63]/64 where X = fft_p(f[b,j,:,i,c]).
// Block = (bi,j), 64 threads (one channel each), FFT in registers.
// ---------------------------------------------------------------------------
__global__ void k1_fft(const float* __restrict__ fre, const float* __restrict__ fim) {
    int bid = blockIdx.x;
    int j = bid & 63, bi = bid >> 6;
    int i = bi & 1,  b = bi >> 1;
    int c = threadIdx.x;   // 0..63

    long base = (long)(b * 64 + j) * 8192 + i * 64 + c;   // + p*128
    float2 x[64];
    #pragma unroll
    for (int p = 0; p < 64; p++) {
        long a = base + (long)p * 128;
        x[p] = make_float2(fre[a] * (1.0f / 64.0f), fim[a] * (1.0f / 64.0f));
    }
    fft64<false>(x);

    long gb = (long)bi * 63 * 4096 + (long)j * 64 + c;
    #pragma unroll
    for (int r = 0; r < 64; r++) {
        constexpr_int:;
        int k = bitrev6(r);
        if (k != 32) {                       // m==63 bin doesn't exist
            int m = (k + 31) & 63;
            g_G[gb + (long)m * 4096] = x[r];
        }
    }
}

// ---------------------------------------------------------------------------
// k2: theta quadrature, packed output (unchanged — passing).
// ---------------------------------------------------------------------------
__global__ void k2_theta(const float* __restrict__ leg_in, const float* __restrict__ w) {
    __shared__ float2 sh_g[64][64];   // [j][c]
    __shared__ float  sh_P[32][64];   // [l][j]

    int m = blockIdx.x, i = blockIdx.y, b = blockIdx.z;
    int tid = threadIdx.x;
    int bi = b * 2 + i;

    long gbase = ((long)bi * 63 + m) * 4096;
    for (int e = tid; e < 4096; e += 256) sh_g[e >> 6][e & 63] = g_G[gbase + e];
    for (int e = tid; e < 2048; e += 256) {
        int l = e >> 6, jj = e & 63;
        sh_P[l][jj] = TWO_PI_F * w[jj] * leg_in[((i * 32 + l) * 63 + m) * 64 + jj];
    }
    __syncthreads();

    int c = tid & 63, lq = tid >> 6;
    int lmin = (m <= 31) ? (31 - m) : (m - 31);
    int nv = 32 - lmin;
    float2 acc[8];
    #pragma unroll
    for (int u = 0; u < 8; u++) acc[u] = make_float2(0.0f, 0.0f);

    for (int jj = 0; jj < 64; jj++) {
        float2 g = sh_g[jj][c];
        #pragma unroll
        for (int u = 0; u < 8; u++) {
            int l = lmin + lq + 4 * u;
            float pl = (l < 32) ? sh_P[l][jj] : 0.0f;
            acc[u].x += pl * g.x;
            acc[u].y += pl * g.y;
        }
    }
    #pragma unroll
    for (int u = 0; u < 8; u++) {
        int lv = lq + 4 * u;
        if (lv < nv) {
            int l = lmin + lv;
            int mm = (m - 31) + l;
            long row = (long)(32 * l * l) + b * (2 * l + 1) + mm;
            g_Ain[row * 128 + i * 64 + c] = acc[u];
        }
    }
}

// ---------------------------------------------------------------------------
// k3: per-l complex GEMM on packed rows, P/Q split (unchanged — passing).
// ---------------------------------------------------------------------------
__global__ void k3_gemm(const float* __restrict__ kre, const float* __restrict__ kim) {
    __shared__ float2     sA[16][64];
    __shared__ ulonglong2 sB[16][64];

    int o = blockIdx.x, rt = blockIdx.y, l = blockIdx.z;
    int nrow = 32 * (2 * l + 1);
    int row0 = rt * 64;
    if (row0 >= nrow) return;

    int tid = threadIdx.x, tx = tid & 15, ty = tid >> 4;
    ull accP[4][4], accQ[4][4];
    #pragma unroll
    for (int ri = 0; ri < 4; ri++)
        #pragma unroll
        for (int ci = 0; ci < 4; ci++) { accP[ri][ci] = 0ull; accQ[ri][ci] = 0ull; }

    long Abase = (long)(32 * l * l) * 128;
    long wbase = (long)l * 16384 + (long)o * 4096;

    for (int k0 = 0; k0 < 128; k0 += 16) {
        #pragma unroll
        for (int t = 0; t < 4; t++) {
            int e = tid + t * 256;
            int rr = e >> 4, kk = e & 15;
            int grow = row0 + rr;
            float2 v = make_float2(0.0f, 0.0f);
            if (grow < nrow) v = g_Ain[Abase + (long)grow * 128 + k0 + kk];
            sA[kk][rr] = v;
        }
        #pragma unroll
        for (int t = 0; t < 4; t++) {
            int e = tid + t * 256;
            int kk = e >> 6, col = e & 63;
            int ic = k0 + kk;
            long a = wbase + (long)(ic >> 6) * 8192 + (ic & 63) * 64 + col;
            float br = kre[a], bim = kim[a];
            sB[kk][col] = make_ulonglong2(pk2(br, br), pk2(bim, bim));
        }
        __syncthreads();
        #pragma unroll
        for (int kk = 0; kk < 16; kk++) {
            ull av[4];
            ulonglong2 bq[4];
            #pragma unroll
            for (int u = 0; u < 4; u++) av[u] = *(const ull*)&sA[kk][ty + 16 * u];
            #pragma unroll
            for (int u = 0; u < 4; u++) bq[u] = sB[kk][tx + 16 * u];
            #pragma unroll
            for (int ri = 0; ri < 4; ri++)
                #pragma unroll
                for (int ci = 0; ci < 4; ci++) {
                    accP[ri][ci] = ffma2(bq[ci].x, av[ri], accP[ri][ci]);
                    accQ[ri][ci] = ffma2(bq[ci].y, av[ri], accQ[ri][ci]);
                }
        }
        __syncthreads();
    }
    #pragma unroll
    for (int ri = 0; ri < 4; ri++) {
        int grow = row0 + ty + 16 * ri;
        if (grow < nrow) {
            #pragma unroll
            for (int ci = 0; ci < 4; ci++)
                g_Aout[Abase + (long)grow * 128 + o * 64 + tx + 16 * ci] =
                    pq(accP[ri][ci], accQ[ri][ci]);
        }
    }
}

// ---------------------------------------------------------------------------
// k4: inverse theta, FFMA2 dup table (unchanged — passing).
// ---------------------------------------------------------------------------
__global__ void k4_itheta(const float* __restrict__ leg_out) {
    __shared__ float2 sh_a[32][64];   // [l][d]
    __shared__ ull    sh_Q[32][64];   // [l][j] dup (q,q)

    int m = blockIdx.x, o = blockIdx.y, b = blockIdx.z;
    int tid = threadIdx.x;
    int lmin = (m <= 31) ? (31 - m) : (m - 31);

    for (int e = tid; e < 2048; e += 256) {
        int l = e >> 6, d = e & 63;
        float2 v = make_float2(0.0f, 0.0f);
        if (l >= lmin) {
            int mm = m - 31 + l;
            long row = (long)(32 * l * l) + b * (2 * l + 1) + mm;
            v = g_Aout[row * 128 + o * 64 + d];
        }
        sh_a[l][d] = v;
    }
    for (int e = tid; e < 2048; e += 256) {
        int l = e >> 6, j = e & 63;
        float q = leg_out[((o * 32 + l) * 63 + m) * 64 + j];
        sh_Q[l][j] = pk2(q, q);
    }
    __syncthreads();

    int d = tid & 63, jq = tid >> 6;
    ull acc[16];
    #pragma unroll
    for (int u = 0; u < 16; u++) acc[u] = 0ull;

    for (int l = lmin; l < 32; l++) {
        ull a = *(const ull*)&sh_a[l][d];
        #pragma unroll
        for (int u = 0; u < 16; u++)
            acc[u] = ffma2(sh_Q[l][jq + 4 * u], a, acc[u]);
    }
    #pragma unroll
    for (int u = 0; u < 16; u++) {
        int j = jq + 4 * u;
        g_G[(long)((b * 64 + j) * 2 + o) * 4032 + m * 64 + d] = upk2(acc[u]);   // H
    }
}

// ---------------------------------------------------------------------------
// k5: inverse FFT over phi (replaces O(N^2) DFT).
// X[(m-31)&63] = H[m], X[32]=0; out[p] = invFFT(X) (scaling cancels: ifft*R).
// Block = ((b*64+j)*2+o), 64 threads (one d each), FFT in registers.
// ---------------------------------------------------------------------------
__global__ void k5_ifft(void* __restrict__ dout, int mode, long out_cap) {
    int bid = blockIdx.x;             // matches k4's H layout
    int d = threadIdx.x;              // 0..63

    long hb = (long)bid * 4032 + d;
    float2 x[64];
    #pragma unroll
    for (int k = 0; k < 64; k++) {
        if (k == 32) x[k] = make_float2(0.0f, 0.0f);
        else {
            int m = (k + 31) & 63;
            x[k] = g_G[hb + (long)m * 64];
        }
    }
    fft64<true>(x);

    int o = bid & 1;
    long bj = (long)(bid >> 1);
    if (mode == 1) {
        float2* out2 = (float2*)dout;
        #pragma unroll
        for (int r = 0; r < 64; r++) {
            int p = bitrev6(r);
            long oi = ((bj * 64 + p) * 2 + o) * 64 + d;
            if (oi < out_cap) out2[oi] = x[r];
        }
    } else {
        float* out1 = (float*)dout;
        #pragma unroll
        for (int r = 0; r < 64; r++) {
            int p = bitrev6(r);
            long oi = ((bj * 64 + p) * 2 + o) * 64 + d;
            if (oi < out_cap) out1[oi] = x[r].x;    // real part
        }
    }
}

// ---------------------------------------------------------------------------
// Host dispatch (identical to the passing R6-R8 logic).
// ---------------------------------------------------------------------------
extern "C" void kernel_launch(void* const* d_in, const int* in_sizes, int n_in,
                              void* d_out, int out_size) {
    if (n_in < 7) return;

    const float* sph[2] = {0, 0};
    const float* ker[2] = {0, 0};
    const float* leg[2] = {0, 0};
    const float* w = 0;
    int ns = 0, nk = 0, nl = 0;

    for (int t = 0; t < n_in; t++) {
        const float* p = (const float*)d_in[t];
        int sz = in_sizes[t];
        if (sz == SZ_SPHERE && ns < 2) sph[ns++] = p;
        else if (sz == SZ_KERNEL && nk < 2) ker[nk++] = p;
        else if (sz == SZ_LEG && nl < 2) leg[nl++] = p;
        else if (sz == SZ_W && !w) w = p;
    }
    if (ns != 2 || nk != 2 || nl != 2 || !w) return;

    bool alpha = (n_in == 7 &&
                  in_sizes[0] == SZ_KERNEL && in_sizes[1] == SZ_KERNEL &&
                  in_sizes[2] == SZ_LEG    && in_sizes[3] == SZ_LEG &&
                  in_sizes[4] == SZ_W      &&
                  in_sizes[5] == SZ_SPHERE && in_sizes[6] == SZ_SPHERE);

    const float *fre, *fim, *kre, *kim;
    if (alpha) { fim = sph[0]; fre = sph[1]; kim = ker[0]; kre = ker[1]; }
    else       { fre = sph[0]; fim = sph[1]; kre = ker[0]; kim = ker[1]; }
    const float* leg_in = leg[0];
    const float* leg_out = leg[1];

    int mode;
    long cap;
    if (out_size == 33554432)      { mode = 1; cap = 16777216; }   // float2 count
    else if (out_size == 16777216) { mode = 0; cap = 16777216; }   // float count
    else                           { mode = 0; cap = (long)out_size; }

    k1_fft   <<<4096, 64>>>(fre, fim);
    k2_theta <<<dim3(63, 2, 32), 256>>>(leg_in, w);
    k3_gemm  <<<dim3(2, 32, 32), 256>>>(kre, kim);
    k4_itheta<<<dim3(63, 2, 32), 256>>>(leg_out);
    k5_ifft  <<<4096, 64>>>(d_out, mode, cap);
}